// round 15
// baseline (speedup 1.0000x reference)
#include <cuda_runtime.h>
#include <cuda_fp16.h>
#include <math.h>
#include <stdint.h>

// ---------------------------------------------------------------------------
// NAS-controller LSTM, persistent kernel v15 = v14 with gsyncA removed from
// the streamer critical path.
//  - streamers: S2 [sync] S3 (signal s3-count) S1 [grid_sync]  — ONE grid
//    barrier per step
//  - crew: act1 [sync] zero-parities(t+2) ; wait s3-count ; act2+logits+sample
//  - s3-count: per-block smem arrivals -> one global atomicAdd per block
//    (two-level fence/strong-op pattern proven in v12); crew volatile-polls
//    (v8-proven) then reads d2/d3 via __ldcg
//  - per-warp 3 x 8KB TMA rings; fp16 a-frag weights; mma.m16n8k16
//  - threefry2x32 partitionable path (verified bit-exact)
// ---------------------------------------------------------------------------

#define HD    2048
#define H4    8192
#define ED    512
#define TT    48
#define MAXS  8
#define NEMB  23
#define NTH   1024
#define NWARPS 32
#define TINYF 1.17549435e-38f

#define NSLOT    3
#define SLICE_B  8192
#define NSTW     8                 // streaming warps per block

// smem layout (bytes)
#define OFF_SAH   0                 // h1 fp16 (4096)
#define OFF_SBH   4096              // h2 fp16
#define OFF_LG    8192
#define OFF_AROW  8224
#define OFF_S3C   8228              // block-local s3 arrival counter
#define OFF_S3B   8232              // g_s3cnt base at launch
#define OFF_MBAR  8240              // 8*3*8 = 192
#define OFF_RING  9216              // 8*3*8192 = 196608
#define SMEM_TOTAL (OFF_RING + NSTW * NSLOT * SLICE_B)   // 205824

// ------------------------- device scratch ----------------------------------
__device__ __half   g_Ws[3u * 512 * 128 * 256];  // swizzled fp16 (96MB)
__device__ float    g_P1[NEMB * H4];
__device__ float    g_d1[4 * H4];    // Whh1.h1 partials, 4-step parity ring
__device__ float    g_d2[4 * H4];    // Whh2.h2
__device__ float    g_d3[4 * H4];    // Wih2.h1new
__device__ float    g_b1[H4];
__device__ float    g_b2[H4];
__device__ unsigned g_s3cnt = 0;     // monotonic S3-completion count
__device__ unsigned g_count = 0;
__device__ unsigned g_gen   = 0;

// ------------------------- grid barrier (v8-proven) -------------------------
__device__ __forceinline__ void grid_sync() {
  __threadfence();
  __syncthreads();
  if (threadIdx.x == 0) {
    volatile unsigned* vg = (volatile unsigned*)&g_gen;
    unsigned gen = *vg;
    __threadfence();
    if (atomicAdd(&g_count, 1u) == (unsigned)(gridDim.x - 1)) {
      g_count = 0u;
      __threadfence();
      atomicAdd(&g_gen, 1u);
    } else {
      while (*vg == gen) { }
    }
  }
  __syncthreads();
}

// ------------------------- mbarrier / bulk copy -----------------------------
__device__ __forceinline__ uint32_t smem_u32(const void* p) {
  uint32_t a;
  asm("{ .reg .u64 t; cvta.to.shared.u64 t, %1; cvt.u32.u64 %0, t; }"
      : "=r"(a) : "l"(p));
  return a;
}
__device__ __forceinline__ void mbar_init(uint32_t a, uint32_t cnt) {
  asm volatile("mbarrier.init.shared.b64 [%0], %1;" :: "r"(a), "r"(cnt) : "memory");
}
__device__ __forceinline__ void mbar_expect(uint32_t a, uint32_t tx) {
  asm volatile("mbarrier.arrive.expect_tx.shared.b64 _, [%0], %1;"
               :: "r"(a), "r"(tx) : "memory");
}
__device__ __forceinline__ void mbar_wait(uint32_t a, unsigned ph) {
  asm volatile(
      "{\n\t.reg .pred P;\n"
      "W%=:\n\t"
      "mbarrier.try_wait.parity.shared.b64 P, [%0], %1;\n\t"
      "@P bra D%=;\n\t"
      "bra W%=;\n"
      "D%=:\n\t}"
      :: "r"(a), "r"(ph) : "memory");
}
__device__ __forceinline__ void bulk_g2s(uint32_t dst, const void* src,
                                         uint32_t bytes, uint32_t bar) {
  asm volatile(
      "cp.async.bulk.shared::cluster.global.mbarrier::complete_tx::bytes "
      "[%0], [%1], %2, [%3];"
      :: "r"(dst), "l"(src), "r"(bytes), "r"(bar) : "memory");
}

// ------------------------- threefry2x32 (verified exact) --------------------
__device__ __forceinline__ unsigned rotl32(unsigned x, int r) {
  return (x << r) | (x >> (32 - r));
}
__device__ __forceinline__ void threefry2x32(unsigned k0, unsigned k1,
                                             unsigned x0, unsigned x1,
                                             unsigned* o0, unsigned* o1) {
  unsigned ks0 = k0, ks1 = k1, ks2 = k0 ^ k1 ^ 0x1BD11BDAu;
  x0 += ks0; x1 += ks1;
  x0 += x1; x1 = rotl32(x1, 13); x1 ^= x0;
  x0 += x1; x1 = rotl32(x1, 15); x1 ^= x0;
  x0 += x1; x1 = rotl32(x1, 26); x1 ^= x0;
  x0 += x1; x1 = rotl32(x1, 6);  x1 ^= x0;
  x0 += ks1; x1 += ks2 + 1u;
  x0 += x1; x1 = rotl32(x1, 17); x1 ^= x0;
  x0 += x1; x1 = rotl32(x1, 29); x1 ^= x0;
  x0 += x1; x1 = rotl32(x1, 16); x1 ^= x0;
  x0 += x1; x1 = rotl32(x1, 24); x1 ^= x0;
  x0 += ks2; x1 += ks0 + 2u;
  x0 += x1; x1 = rotl32(x1, 13); x1 ^= x0;
  x0 += x1; x1 = rotl32(x1, 15); x1 ^= x0;
  x0 += x1; x1 = rotl32(x1, 26); x1 ^= x0;
  x0 += x1; x1 = rotl32(x1, 6);  x1 ^= x0;
  x0 += ks0; x1 += ks1 + 3u;
  x0 += x1; x1 = rotl32(x1, 17); x1 ^= x0;
  x0 += x1; x1 = rotl32(x1, 29); x1 ^= x0;
  x0 += x1; x1 = rotl32(x1, 16); x1 ^= x0;
  x0 += x1; x1 = rotl32(x1, 24); x1 ^= x0;
  x0 += ks1; x1 += ks2 + 4u;
  x0 += x1; x1 = rotl32(x1, 13); x1 ^= x0;
  x0 += x1; x1 = rotl32(x1, 15); x1 ^= x0;
  x0 += x1; x1 = rotl32(x1, 26); x1 ^= x0;
  x0 += x1; x1 = rotl32(x1, 6);  x1 ^= x0;
  x0 += ks2; x1 += ks0 + 5u;
  *o0 = x0; *o1 = x1;
}

__device__ __forceinline__ float sigm(float x) { return 1.0f / (1.0f + expf(-x)); }

// ------------------------- main persistent kernel ---------------------------
__global__ void __launch_bounds__(NTH, 1)
nas_lstm_kernel(const float* __restrict__ emb,
                const float* __restrict__ Wih1, const float* __restrict__ Whh1,
                const float* __restrict__ bih1, const float* __restrict__ bhh1,
                const float* __restrict__ Wih2, const float* __restrict__ Whh2,
                const float* __restrict__ bih2, const float* __restrict__ bhh2,
                const float* __restrict__ Wout, const float* __restrict__ bout,
                float* __restrict__ out) {
  extern __shared__ __align__(16) char sm[];
  const uint32_t smu = smem_u32(sm);

  const int tid  = threadIdx.x;
  const int b    = blockIdx.x;
  const int w    = tid >> 5;
  const int lane = tid & 31;
  const int nblk = gridDim.x;
  const int totw = nblk * NWARPS;
  const int wgl  = w * nblk + b;

  __half* sAh = (__half*)(sm + OFF_SAH);
  __half* sBh = (__half*)(sm + OFF_SBH);
  float*  sLG = (float*)(sm + OFF_LG);
  int*    sAR = (int*)(sm + OFF_AROW);
  unsigned* sS3 = (unsigned*)(sm + OFF_S3C);
  unsigned* sS3B = (unsigned*)(sm + OFF_S3B);

  const bool strm = (w < NSTW);
  const uint32_t bar  = smu + OFF_MBAR + (uint32_t)w * NSLOT * 8;
  const uint32_t ring = smu + OFF_RING + (uint32_t)w * NSLOT * SLICE_B;
  const int ringoff   = OFF_RING + w * NSLOT * SLICE_B;

  const int nwst = NSTW * nblk;
  const int g    = strm ? (w * nblk + b) : 0;
  const int nU   = strm ? ((g < 1024) ? ((1024 - 1 - g) / nwst + 1) : 0) : 0;
  const int L    = 12 * nU;
  const int TOTAL = TT * L;

  const int a = tid - NSTW * 32;          // crew index 0..767

  // ---------------- init ----------------
  if (tid == 0) {
    *sAR = -1;
    *sS3 = 0u;
    *sS3B = atomicAdd(&g_s3cnt, 0u);      // launch base (replay-safe)
  }
  for (int i = tid; i < HD; i += NTH) {
    sAh[i] = __float2half_rn(0.f);
    sBh[i] = __float2half_rn(0.f);
  }
  for (int i = tid; i < NSTW * NSLOT; i += NTH)
    mbar_init(smu + OFF_MBAR + (uint32_t)i * 8, 1u);
  __syncthreads();
  if (tid == 0)
    asm volatile("fence.proxy.async.shared::cta;" ::: "memory");

  for (int i = b * NTH + tid; i < 4 * H4; i += nblk * NTH) {
    g_d1[i] = 0.f; g_d2[i] = 0.f; g_d3[i] = 0.f;
  }
  for (int i = b * NTH + tid; i < H4; i += nblk * NTH) {
    g_b1[i] = bih1[i] + bhh1[i];
    g_b2[i] = bih2[i] + bhh2[i];
  }

  // fp32 -> fp16 a-frag swizzle (verified)
  {
    uint2* dst = (uint2*)g_Ws;
    const long NQ = 3L * 512 * 8 * 512;
    for (long q = (long)b * NTH + tid; q < NQ; q += (long)nblk * NTH) {
      const int cg   = (int)(q & 511);
      const int r    = (int)((q >> 9) & 7);
      const int tile = (int)((q >> 12) & 511);
      const int mat  = (int)(q >> 21);
      const int c    = cg << 2;
      const int j    = cg >> 2;
      const int Lr   = (r << 2) + ((cg & 1) << 1);
      const int o    = (cg & 2) ? 1 : 0;
      const float* src = (mat == 0) ? Whh1 : (mat == 1) ? Whh2 : Wih2;
      const int R1 = (tile << 4) + r;
      float4 v1 = __ldg((const float4*)(src + ((size_t)R1 << 11) + c));
      float4 v2 = __ldg((const float4*)(src + ((size_t)(R1 + 8) << 11) + c));
      __half2 a1 = __floats2half2_rn(v1.x, v1.y);
      __half2 a2 = __floats2half2_rn(v2.x, v2.y);
      __half2 b1h = __floats2half2_rn(v1.z, v1.w);
      __half2 b2h = __floats2half2_rn(v2.z, v2.w);
      const long blk = ((long)(mat << 9 | tile) * 128 + j) * 64;
      uint2 u2a, u2b;
      u2a.x = *(unsigned*)&a1; u2a.y = *(unsigned*)&a2;
      u2b.x = *(unsigned*)&b1h; u2b.y = *(unsigned*)&b2h;
      dst[blk + (Lr << 1) + o]       = u2a;
      dst[blk + ((Lr + 1) << 1) + o] = u2b;
    }
  }

  // P1 = emb @ Wih1^T (warp per row, fp32)
  for (int r = wgl; r < H4; r += totw) {
    float wreg[16];
    const float* wrow = Wih1 + (size_t)r * ED;
#pragma unroll
    for (int i = 0; i < 16; i++) wreg[i] = wrow[lane + i * 32];
    for (int m = 0; m < NEMB; m++) {
      const float* er = emb + m * ED;
      float p = 0.f;
#pragma unroll
      for (int i = 0; i < 16; i++) p += wreg[i] * er[lane + i * 32];
#pragma unroll
      for (int off = 16; off; off >>= 1) p += __shfl_xor_sync(0xffffffffu, p, off);
      if (lane == 0) g_P1[m * H4 + r] = p;
    }
  }
  grid_sync();

  // stream cursors
  int iss = 0, s_seg = 0, s_k = 0, s_q = 0, i_slot = 0, con_slot = 0;
  unsigned ph = 0;
  float c1r[3] = {0.f, 0.f, 0.f};
  float c2r[3] = {0.f, 0.f, 0.f};

#define ISSUE_NEXT()                                                           \
  do {                                                                         \
    if (iss < TOTAL) {                                                         \
      if (lane == 0) {                                                         \
        const int mt_ = (s_seg == 0) ? 1 : ((s_seg == 1) ? 2 : 0);             \
        const int u_ = g + s_k * nwst;                                         \
        const int T_ = u_ >> 1, kh_ = u_ & 1;                                  \
        const char* src_ = (const char*)g_Ws                                   \
            + (((size_t)((mt_ << 9) | T_)) << 16)                              \
            + ((size_t)kh_ << 15) + ((size_t)s_q << 13);                       \
        mbar_expect(bar + i_slot * 8, SLICE_B);                                \
        bulk_g2s(ring + i_slot * SLICE_B, src_, SLICE_B, bar + i_slot * 8);    \
      }                                                                        \
      if (++s_q == 4) {                                                        \
        s_q = 0;                                                               \
        if (++s_k == nU) { s_k = 0; if (++s_seg == 3) s_seg = 0; }             \
      }                                                                        \
      i_slot = (i_slot + 1 == NSLOT) ? 0 : i_slot + 1;                         \
      iss++;                                                                   \
    }                                                                          \
  } while (0)

#define CONSUME_SEG(HSM, DPTR)                                                 \
  do {                                                                         \
    for (int k = 0; k < nU; k++) {                                             \
      const int u = g + k * nwst;                                              \
      const int T = u >> 1;                                                    \
      const int kh = u & 1;                                                    \
      const unsigned* hpk = (const unsigned*)(HSM) + (kh << 9) + (lane & 3);   \
      float e0 = 0.f, e1 = 0.f, e2 = 0.f, e3 = 0.f;                            \
      for (int q3 = 0; q3 < 4; q3++) {                                         \
        mbar_wait(bar + con_slot * 8, (ph >> con_slot) & 1u);                  \
        ph ^= (1u << con_slot);                                                \
        const uint4* wp = (const uint4*)(sm + ringoff + con_slot * SLICE_B) + lane; \
        const unsigned* hq = hpk + (q3 << 7);                                  \
        _Pragma("unroll 8")                                                    \
        for (int j = 0; j < 16; j++) {                                         \
          uint4 aa = wp[j * 32];                                               \
          unsigned f0 = hq[j << 3];                                            \
          unsigned f1 = hq[(j << 3) + 4];                                      \
          asm volatile(                                                        \
              "mma.sync.aligned.m16n8k16.row.col.f32.f16.f16.f32 "             \
              "{%0,%1,%2,%3}, {%4,%5,%6,%7}, {%8,%9}, {%0,%1,%2,%3};"          \
              : "+f"(e0), "+f"(e1), "+f"(e2), "+f"(e3)                         \
              : "r"(aa.x), "r"(aa.y), "r"(aa.z), "r"(aa.w), "r"(f0), "r"(f1)); \
        }                                                                      \
        con_slot = (con_slot + 1 == NSLOT) ? 0 : con_slot + 1;                 \
        ISSUE_NEXT();                                                          \
      }                                                                        \
      if ((lane & 3) == 0) {                                                   \
        atomicAdd(&(DPTR)[(T << 4) + (lane >> 2)], e0);                        \
        atomicAdd(&(DPTR)[(T << 4) + 8 + (lane >> 2)], e2);                    \
      }                                                                        \
    }                                                                          \
  } while (0)

  if (strm && L > 0)
    for (int k = 0; k < NSLOT; k++) ISSUE_NEXT();

  const int sizes[4] = {8, 6, 4, 5};
  const int offs[4]  = {0, 8, 14, 18};
  const unsigned s3base = *sS3B;

  for (int t = 0; t < TT; t++) {
    const int pb = t & 3;
    const int pn = (t + 1) & 3;
    const int pz = (t + 2) & 3;
    float* d1 = g_d1 + pb * H4;
    float* d1n = g_d1 + pn * H4;
    float* d2 = g_d2 + pb * H4;
    float* d3 = g_d3 + pb * H4;

    // ======== phase 1a: [S2 = Whh2 . h2prev] || [act1] ========
    if (strm) {
      CONSUME_SEG(sBh, d2);
    } else {
      const int arow = *sAR;
      const float* P = (arow >= 0) ? (g_P1 + (size_t)arow * H4) : (const float*)0;
#pragma unroll
      for (int k = 0; k < 3; k++) {
        const int u = a + k * 768;
        if (u < HD) {
          float di = __ldcg(&d1[u])        + __ldcg(&g_b1[u]);
          float df = __ldcg(&d1[u + 2048]) + __ldcg(&g_b1[u + 2048]);
          float dg = __ldcg(&d1[u + 4096]) + __ldcg(&g_b1[u + 4096]);
          float dz = __ldcg(&d1[u + 6144]) + __ldcg(&g_b1[u + 6144]);
          if (P) {
            di += __ldcg(&P[u]);        df += __ldcg(&P[u + 2048]);
            dg += __ldcg(&P[u + 4096]); dz += __ldcg(&P[u + 6144]);
          }
          float c = sigm(df) * c1r[k] + sigm(di) * tanhf(dg);
          c1r[k] = c;
          sAh[u] = __float2half_rn(sigm(dz) * tanhf(c));
        }
      }
    }
    __syncthreads();   // sAh (h1 new) ready for S3

    // ======== streamers: S3 -> d3, signal, then S1 -> d1' ========
    if (strm) {
      CONSUME_SEG(sAh, d3);
      // signal S3 completion (two-level strong pattern, v12-proven)
      if (lane == 0) {
        __threadfence();
        unsigned old = atomicAdd(sS3, 1u);
        if ((old + 1u) % (unsigned)NSTW == 0u) {
          __threadfence();
          atomicAdd(&g_s3cnt, 1u);
        }
      }
      CONSUME_SEG(sAh, d1n);
    } else {
      // crew: zero parities (t+2) of d1,d2,d3 (used at t+1/t+2; ordered by
      // gsyncB(t) before any step-(t+1) writes)
      for (int z = b * 768 + a; z < 3 * H4; z += nblk * 768) {
        if (z < H4)            __stcg(&g_d1[pz * H4 + z], 0.f);
        else if (z < 2 * H4)   __stcg(&g_d2[pz * H4 + (z - H4)], 0.f);
        else                   __stcg(&g_d3[pz * H4 + (z - 2 * H4)], 0.f);
      }
      // wait for all blocks' S3 (d2,d3 complete)
      if (a == 0) {
        volatile unsigned* vc = (volatile unsigned*)&g_s3cnt;
        const unsigned target = s3base + (unsigned)nblk * (unsigned)(t + 1);
        while ((int)(*vc - target) < 0) { }
        __threadfence();
      }
      asm volatile("bar.sync 1, 768;" ::: "memory");
      // act2 -> h2
#pragma unroll
      for (int k = 0; k < 3; k++) {
        const int u = a + k * 768;
        if (u < HD) {
          float di = __ldcg(&d2[u])        + __ldcg(&d3[u])        + __ldcg(&g_b2[u]);
          float df = __ldcg(&d2[u + 2048]) + __ldcg(&d3[u + 2048]) + __ldcg(&g_b2[u + 2048]);
          float dg = __ldcg(&d2[u + 4096]) + __ldcg(&d3[u + 4096]) + __ldcg(&g_b2[u + 4096]);
          float dz = __ldcg(&d2[u + 6144]) + __ldcg(&d3[u + 6144]) + __ldcg(&g_b2[u + 6144]);
          float c = sigm(df) * c2r[k] + sigm(di) * tanhf(dg);
          c2r[k] = c;
          sBh[u] = __float2half_rn(sigm(dz) * tanhf(c));
        }
      }
      asm volatile("bar.sync 1, 768;" ::: "memory");   // sBh ready (crew)
      if (w < 16) {
        const int j = w - 8;
        const float4* wr = (const float4*)(Wout + ((size_t)t * MAXS + j) * HD);
        const __half2* h2p = (const __half2*)sBh;
        float p = 0.f;
#pragma unroll 4
        for (int i = lane; i < HD / 4; i += 32) {
          float4 aa = __ldg(&wr[i]);
          float2 xf = __half22float2(h2p[2 * i]);
          float2 yf = __half22float2(h2p[2 * i + 1]);
          p += aa.x * xf.x + aa.y * xf.y + aa.z * yf.x + aa.w * yf.y;
        }
#pragma unroll
        for (int off = 16; off; off >>= 1) p += __shfl_xor_sync(0xffffffffu, p, off);
        if (lane == 0) sLG[j] = p + bout[t * MAXS + j];
      }
      asm volatile("bar.sync 1, 768;" ::: "memory");   // logits ready
      if (a == 0) {
        const int tp = t & 3;
        const int sz = sizes[tp];
        float l[8];
#pragma unroll
        for (int j = 0; j < 8; j++) l[j] = (j < sz) ? sLG[j] : -1e9f;

        unsigned k0, k1;
        threefry2x32(0u, 1u, 0u, (unsigned)t, &k0, &k1);
        unsigned bits[8];
#pragma unroll
        for (int i = 0; i < 8; i++) {
          unsigned aa, bb;
          threefry2x32(k0, k1, 0u, (unsigned)i, &aa, &bb);
          bits[i] = aa ^ bb;
        }
        float gmb[8];
#pragma unroll
        for (int j = 0; j < 8; j++) {
          unsigned fb = (bits[j] >> 9) | 0x3f800000u;
          float uu = __uint_as_float(fb) - 1.0f;
          uu = fmaxf(TINYF, uu + TINYF);
          gmb[j] = -logf(-logf(uu));
        }
        int best = 0;
        float bv = l[0] + gmb[0];
#pragma unroll
        for (int j = 1; j < 8; j++) {
          float v = l[j] + gmb[j];
          if (v > bv) { bv = v; best = j; }
        }
        float m = l[0];
#pragma unroll
        for (int j = 1; j < 8; j++) m = fmaxf(m, l[j]);
        float s = 0.f;
#pragma unroll
        for (int j = 0; j < 8; j++) s += expf(l[j] - m);
        float prob = expf(l[best] - m) / s;

        *sAR = offs[tp] + best;
        if (b == 0) {
          out[t]      = (float)best;
          out[TT + t] = prob;
        }
      }
    }
    grid_sync();   // gsyncB: d1' complete grid-wide; sAR published in-block
  }
}

// ------------------------- launch -------------------------------------------
extern "C" void kernel_launch(void* const* d_in, const int* in_sizes, int n_in,
                              void* d_out, int out_size) {
  const float* emb  = (const float*)d_in[0];
  const float* Wih1 = (const float*)d_in[1];
  const float* Whh1 = (const float*)d_in[2];
  const float* bih1 = (const float*)d_in[3];
  const float* bhh1 = (const float*)d_in[4];
  const float* Wih2 = (const float*)d_in[5];
  const float* Whh2 = (const float*)d_in[6];
  const float* bih2 = (const float*)d_in[7];
  const float* bhh2 = (const float*)d_in[8];
  const float* Wout = (const float*)d_in[9];
  const float* bout = (const float*)d_in[10];
  (void)in_sizes; (void)n_in; (void)out_size;

  static int configured = 0;
  if (!configured) {
    cudaFuncSetAttribute(nas_lstm_kernel,
                         cudaFuncAttributeMaxDynamicSharedMemorySize, SMEM_TOTAL);
    configured = 1;
  }

  int dev = 0;
  cudaGetDevice(&dev);
  int sms = 0;
  cudaDeviceGetAttribute(&sms, cudaDevAttrMultiProcessorCount, dev);
  int occ = 0;
  cudaOccupancyMaxActiveBlocksPerMultiprocessor(&occ, nas_lstm_kernel, NTH,
                                                SMEM_TOTAL);
  if (occ < 1) occ = 1;
  int nblk = sms * occ;
  if (nblk > 128) nblk = 128;
  if (nblk < 2) nblk = 2;

  nas_lstm_kernel<<<nblk, NTH, SMEM_TOTAL>>>(emb, Wih1, Whh1, bih1, bhh1,
                                             Wih2, Whh2, bih2, bhh2,
                                             Wout, bout, (float*)d_out);
}

// round 16
// speedup vs baseline: 1.0113x; 1.0113x over previous
#include <cuda_runtime.h>
#include <cuda_fp16.h>
#include <math.h>
#include <stdint.h>

// ---------------------------------------------------------------------------
// NAS-controller LSTM, persistent kernel v16 = v14 + dual-accumulator HMMA
// (breaks the 64-deep dependent mma chain that serialized streamers at ~24cyc
// per link; two interleaved chains halve the latency-bound segment time).
//  - role split: warps 0-7 stream+HMMA, warps 8-31 acts/logits/sample/zeroing
//  - schedule: [S2 || act1] sync [S3 || zero-d1'] gsyncA [S1' || act2+sample]
//    gsyncB  (v14-proven)
//  - per-warp 3 x 8KB TMA rings; fp16 a-frag weights (L2-resident)
//  - atomicAdd partials (2 addends/row -> deterministic); v8-proven barrier
//  - threefry2x32 partitionable path (verified bit-exact)
// ---------------------------------------------------------------------------

#define HD    2048
#define H4    8192
#define ED    512
#define TT    48
#define MAXS  8
#define NEMB  23
#define NTH   1024
#define NWARPS 32
#define TINYF 1.17549435e-38f

#define NSLOT    3
#define SLICE_B  8192
#define NSTW     8                 // streaming warps per block

// smem layout (bytes)
#define OFF_SAH   0                 // h1 fp16 (4096)
#define OFF_SBH   4096              // h2 fp16
#define OFF_LG    8192
#define OFF_AROW  8224
#define OFF_MBAR  8240              // 8*3*8 = 192
#define OFF_RING  9216              // 8*3*8192 = 196608
#define SMEM_TOTAL (OFF_RING + NSTW * NSLOT * SLICE_B)   // 205824

// ------------------------- device scratch ----------------------------------
__device__ __half   g_Ws[3u * 512 * 128 * 256];  // swizzled fp16 (96MB)
__device__ float    g_P1[NEMB * H4];
__device__ float    g_d1[4 * H4];    // Whh1.h1 partials, 4-step parity ring
__device__ float    g_d2[4 * H4];    // Whh2.h2
__device__ float    g_d3[4 * H4];    // Wih2.h1new
__device__ float    g_b1[H4];
__device__ float    g_b2[H4];
__device__ unsigned g_count = 0;
__device__ unsigned g_gen   = 0;

// ------------------------- grid barrier (v8-proven) -------------------------
__device__ __forceinline__ void grid_sync() {
  __threadfence();
  __syncthreads();
  if (threadIdx.x == 0) {
    volatile unsigned* vg = (volatile unsigned*)&g_gen;
    unsigned gen = *vg;
    __threadfence();
    if (atomicAdd(&g_count, 1u) == (unsigned)(gridDim.x - 1)) {
      g_count = 0u;
      __threadfence();
      atomicAdd(&g_gen, 1u);
    } else {
      while (*vg == gen) { }
    }
  }
  __syncthreads();
}

// ------------------------- mbarrier / bulk copy -----------------------------
__device__ __forceinline__ uint32_t smem_u32(const void* p) {
  uint32_t a;
  asm("{ .reg .u64 t; cvta.to.shared.u64 t, %1; cvt.u32.u64 %0, t; }"
      : "=r"(a) : "l"(p));
  return a;
}
__device__ __forceinline__ void mbar_init(uint32_t a, uint32_t cnt) {
  asm volatile("mbarrier.init.shared.b64 [%0], %1;" :: "r"(a), "r"(cnt) : "memory");
}
__device__ __forceinline__ void mbar_expect(uint32_t a, uint32_t tx) {
  asm volatile("mbarrier.arrive.expect_tx.shared.b64 _, [%0], %1;"
               :: "r"(a), "r"(tx) : "memory");
}
__device__ __forceinline__ void mbar_wait(uint32_t a, unsigned ph) {
  asm volatile(
      "{\n\t.reg .pred P;\n"
      "W%=:\n\t"
      "mbarrier.try_wait.parity.shared.b64 P, [%0], %1;\n\t"
      "@P bra D%=;\n\t"
      "bra W%=;\n"
      "D%=:\n\t}"
      :: "r"(a), "r"(ph) : "memory");
}
__device__ __forceinline__ void bulk_g2s(uint32_t dst, const void* src,
                                         uint32_t bytes, uint32_t bar) {
  asm volatile(
      "cp.async.bulk.shared::cluster.global.mbarrier::complete_tx::bytes "
      "[%0], [%1], %2, [%3];"
      :: "r"(dst), "l"(src), "r"(bytes), "r"(bar) : "memory");
}

// ------------------------- threefry2x32 (verified exact) --------------------
__device__ __forceinline__ unsigned rotl32(unsigned x, int r) {
  return (x << r) | (x >> (32 - r));
}
__device__ __forceinline__ void threefry2x32(unsigned k0, unsigned k1,
                                             unsigned x0, unsigned x1,
                                             unsigned* o0, unsigned* o1) {
  unsigned ks0 = k0, ks1 = k1, ks2 = k0 ^ k1 ^ 0x1BD11BDAu;
  x0 += ks0; x1 += ks1;
  x0 += x1; x1 = rotl32(x1, 13); x1 ^= x0;
  x0 += x1; x1 = rotl32(x1, 15); x1 ^= x0;
  x0 += x1; x1 = rotl32(x1, 26); x1 ^= x0;
  x0 += x1; x1 = rotl32(x1, 6);  x1 ^= x0;
  x0 += ks1; x1 += ks2 + 1u;
  x0 += x1; x1 = rotl32(x1, 17); x1 ^= x0;
  x0 += x1; x1 = rotl32(x1, 29); x1 ^= x0;
  x0 += x1; x1 = rotl32(x1, 16); x1 ^= x0;
  x0 += x1; x1 = rotl32(x1, 24); x1 ^= x0;
  x0 += ks2; x1 += ks0 + 2u;
  x0 += x1; x1 = rotl32(x1, 13); x1 ^= x0;
  x0 += x1; x1 = rotl32(x1, 15); x1 ^= x0;
  x0 += x1; x1 = rotl32(x1, 26); x1 ^= x0;
  x0 += x1; x1 = rotl32(x1, 6);  x1 ^= x0;
  x0 += ks0; x1 += ks1 + 3u;
  x0 += x1; x1 = rotl32(x1, 17); x1 ^= x0;
  x0 += x1; x1 = rotl32(x1, 29); x1 ^= x0;
  x0 += x1; x1 = rotl32(x1, 16); x1 ^= x0;
  x0 += x1; x1 = rotl32(x1, 24); x1 ^= x0;
  x0 += ks1; x1 += ks2 + 4u;
  x0 += x1; x1 = rotl32(x1, 13); x1 ^= x0;
  x0 += x1; x1 = rotl32(x1, 15); x1 ^= x0;
  x0 += x1; x1 = rotl32(x1, 26); x1 ^= x0;
  x0 += x1; x1 = rotl32(x1, 6);  x1 ^= x0;
  x0 += ks2; x1 += ks0 + 5u;
  *o0 = x0; *o1 = x1;
}

__device__ __forceinline__ float sigm(float x) { return 1.0f / (1.0f + expf(-x)); }

// ------------------------- main persistent kernel ---------------------------
__global__ void __launch_bounds__(NTH, 1)
nas_lstm_kernel(const float* __restrict__ emb,
                const float* __restrict__ Wih1, const float* __restrict__ Whh1,
                const float* __restrict__ bih1, const float* __restrict__ bhh1,
                const float* __restrict__ Wih2, const float* __restrict__ Whh2,
                const float* __restrict__ bih2, const float* __restrict__ bhh2,
                const float* __restrict__ Wout, const float* __restrict__ bout,
                float* __restrict__ out) {
  extern __shared__ __align__(16) char sm[];
  const uint32_t smu = smem_u32(sm);

  const int tid  = threadIdx.x;
  const int b    = blockIdx.x;
  const int w    = tid >> 5;
  const int lane = tid & 31;
  const int nblk = gridDim.x;
  const int totw = nblk * NWARPS;
  const int wgl  = w * nblk + b;

  __half* sAh = (__half*)(sm + OFF_SAH);
  __half* sBh = (__half*)(sm + OFF_SBH);
  float*  sLG = (float*)(sm + OFF_LG);
  int*    sAR = (int*)(sm + OFF_AROW);

  const bool strm = (w < NSTW);
  const uint32_t bar  = smu + OFF_MBAR + (uint32_t)w * NSLOT * 8;
  const uint32_t ring = smu + OFF_RING + (uint32_t)w * NSLOT * SLICE_B;
  const int ringoff   = OFF_RING + w * NSLOT * SLICE_B;

  const int nwst = NSTW * nblk;
  const int g    = strm ? (w * nblk + b) : 0;
  const int nU   = strm ? ((g < 1024) ? ((1024 - 1 - g) / nwst + 1) : 0) : 0;
  const int L    = 12 * nU;
  const int TOTAL = TT * L;

  const int a = tid - NSTW * 32;          // crew index 0..767

  // ---------------- init ----------------
  for (int i = tid; i < HD; i += NTH) {
    sAh[i] = __float2half_rn(0.f);
    sBh[i] = __float2half_rn(0.f);
  }
  for (int i = tid; i < NSTW * NSLOT; i += NTH)
    mbar_init(smu + OFF_MBAR + (uint32_t)i * 8, 1u);
  if (tid == 0) *sAR = -1;
  __syncthreads();
  if (tid == 0)
    asm volatile("fence.proxy.async.shared::cta;" ::: "memory");

  for (int i = b * NTH + tid; i < 4 * H4; i += nblk * NTH) {
    g_d1[i] = 0.f; g_d2[i] = 0.f; g_d3[i] = 0.f;
  }
  for (int i = b * NTH + tid; i < H4; i += nblk * NTH) {
    g_b1[i] = bih1[i] + bhh1[i];
    g_b2[i] = bih2[i] + bhh2[i];
  }

  // fp32 -> fp16 a-frag swizzle (verified)
  {
    uint2* dst = (uint2*)g_Ws;
    const long NQ = 3L * 512 * 8 * 512;
    for (long q = (long)b * NTH + tid; q < NQ; q += (long)nblk * NTH) {
      const int cg   = (int)(q & 511);
      const int r    = (int)((q >> 9) & 7);
      const int tile = (int)((q >> 12) & 511);
      const int mat  = (int)(q >> 21);
      const int c    = cg << 2;
      const int j    = cg >> 2;
      const int Lr   = (r << 2) + ((cg & 1) << 1);
      const int o    = (cg & 2) ? 1 : 0;
      const float* src = (mat == 0) ? Whh1 : (mat == 1) ? Whh2 : Wih2;
      const int R1 = (tile << 4) + r;
      float4 v1 = __ldg((const float4*)(src + ((size_t)R1 << 11) + c));
      float4 v2 = __ldg((const float4*)(src + ((size_t)(R1 + 8) << 11) + c));
      __half2 a1 = __floats2half2_rn(v1.x, v1.y);
      __half2 a2 = __floats2half2_rn(v2.x, v2.y);
      __half2 b1h = __floats2half2_rn(v1.z, v1.w);
      __half2 b2h = __floats2half2_rn(v2.z, v2.w);
      const long blk = ((long)(mat << 9 | tile) * 128 + j) * 64;
      uint2 u2a, u2b;
      u2a.x = *(unsigned*)&a1; u2a.y = *(unsigned*)&a2;
      u2b.x = *(unsigned*)&b1h; u2b.y = *(unsigned*)&b2h;
      dst[blk + (Lr << 1) + o]       = u2a;
      dst[blk + ((Lr + 1) << 1) + o] = u2b;
    }
  }

  // P1 = emb @ Wih1^T (warp per row, fp32)
  for (int r = wgl; r < H4; r += totw) {
    float wreg[16];
    const float* wrow = Wih1 + (size_t)r * ED;
#pragma unroll
    for (int i = 0; i < 16; i++) wreg[i] = wrow[lane + i * 32];
    for (int m = 0; m < NEMB; m++) {
      const float* er = emb + m * ED;
      float p = 0.f;
#pragma unroll
      for (int i = 0; i < 16; i++) p += wreg[i] * er[lane + i * 32];
#pragma unroll
      for (int off = 16; off; off >>= 1) p += __shfl_xor_sync(0xffffffffu, p, off);
      if (lane == 0) g_P1[m * H4 + r] = p;
    }
  }
  grid_sync();

  // stream cursors
  int iss = 0, s_seg = 0, s_k = 0, s_q = 0, i_slot = 0, con_slot = 0;
  unsigned ph = 0;
  float c1r[3] = {0.f, 0.f, 0.f};
  float c2r[3] = {0.f, 0.f, 0.f};

#define ISSUE_NEXT()                                                           \
  do {                                                                         \
    if (iss < TOTAL) {                                                         \
      if (lane == 0) {                                                         \
        const int mt_ = (s_seg == 0) ? 1 : ((s_seg == 1) ? 2 : 0);             \
        const int u_ = g + s_k * nwst;                                         \
        const int T_ = u_ >> 1, kh_ = u_ & 1;                                  \
        const char* src_ = (const char*)g_Ws                                   \
            + (((size_t)((mt_ << 9) | T_)) << 16)                              \
            + ((size_t)kh_ << 15) + ((size_t)s_q << 13);                       \
        mbar_expect(bar + i_slot * 8, SLICE_B);                                \
        bulk_g2s(ring + i_slot * SLICE_B, src_, SLICE_B, bar + i_slot * 8);    \
      }                                                                        \
      if (++s_q == 4) {                                                        \
        s_q = 0;                                                               \
        if (++s_k == nU) { s_k = 0; if (++s_seg == 3) s_seg = 0; }             \
      }                                                                        \
      i_slot = (i_slot + 1 == NSLOT) ? 0 : i_slot + 1;                         \
      iss++;                                                                   \
    }                                                                          \
  } while (0)

// consume nU units with DUAL accumulator chains (j even/odd) -> halves the
// dependent HMMA chain; sum chains before the (deterministic) atomicAdd.
#define CONSUME_SEG(HSM, DPTR)                                                 \
  do {                                                                         \
    for (int k = 0; k < nU; k++) {                                             \
      const int u = g + k * nwst;                                              \
      const int T = u >> 1;                                                    \
      const int kh = u & 1;                                                    \
      const unsigned* hpk = (const unsigned*)(HSM) + (kh << 9) + (lane & 3);   \
      float p0 = 0.f, p1 = 0.f, p2 = 0.f, p3 = 0.f;                            \
      float q0 = 0.f, q1 = 0.f, q2 = 0.f, q3r = 0.f;                           \
      for (int q3 = 0; q3 < 4; q3++) {                                         \
        mbar_wait(bar + con_slot * 8, (ph >> con_slot) & 1u);                  \
        ph ^= (1u << con_slot);                                                \
        const uint4* wp = (const uint4*)(sm + ringoff + con_slot * SLICE_B) + lane; \
        const unsigned* hq = hpk + (q3 << 7);                                  \
        _Pragma("unroll")                                                      \
        for (int j = 0; j < 16; j += 2) {                                      \
          uint4 aa = wp[j * 32];                                               \
          unsigned f0 = hq[j << 3];                                            \
          unsigned f1 = hq[(j << 3) + 4];                                      \
          asm volatile(                                                        \
              "mma.sync.aligned.m16n8k16.row.col.f32.f16.f16.f32 "             \
              "{%0,%1,%2,%3}, {%4,%5,%6,%7}, {%8,%9}, {%0,%1,%2,%3};"          \
              : "+f"(p0), "+f"(p1), "+f"(p2), "+f"(p3)                         \
              : "r"(aa.x), "r"(aa.y), "r"(aa.z), "r"(aa.w), "r"(f0), "r"(f1)); \
          uint4 ab = wp[(j + 1) * 32];                                         \
          unsigned f2 = hq[(j + 1) << 3];                                      \
          unsigned f3 = hq[((j + 1) << 3) + 4];                                \
          asm volatile(                                                        \
              "mma.sync.aligned.m16n8k16.row.col.f32.f16.f16.f32 "             \
              "{%0,%1,%2,%3}, {%4,%5,%6,%7}, {%8,%9}, {%0,%1,%2,%3};"          \
              : "+f"(q0), "+f"(q1), "+f"(q2), "+f"(q3r)                        \
              : "r"(ab.x), "r"(ab.y), "r"(ab.z), "r"(ab.w), "r"(f2), "r"(f3)); \
        }                                                                      \
        con_slot = (con_slot + 1 == NSLOT) ? 0 : con_slot + 1;                 \
        ISSUE_NEXT();                                                          \
      }                                                                        \
      if ((lane & 3) == 0) {                                                   \
        atomicAdd(&(DPTR)[(T << 4) + (lane >> 2)], p0 + q0);                   \
        atomicAdd(&(DPTR)[(T << 4) + 8 + (lane >> 2)], p2 + q2);               \
      }                                                                        \
    }                                                                          \
  } while (0)

  if (strm && L > 0)
    for (int k = 0; k < NSLOT; k++) ISSUE_NEXT();

  const int sizes[4] = {8, 6, 4, 5};
  const int offs[4]  = {0, 8, 14, 18};

  for (int t = 0; t < TT; t++) {
    const int pb = t & 3;
    const int pn = (t + 1) & 3;
    float* d1 = g_d1 + pb * H4;
    float* d1n = g_d1 + pn * H4;
    float* d2 = g_d2 + pb * H4;
    float* d3 = g_d3 + pb * H4;

    // ======== phase 1a: [S2 = Whh2 . h2prev] || [act1] ========
    if (strm) {
      CONSUME_SEG(sBh, d2);
    } else {
      const int arow = *sAR;
      const float* P = (arow >= 0) ? (g_P1 + (size_t)arow * H4) : (const float*)0;
#pragma unroll
      for (int k = 0; k < 3; k++) {
        const int u = a + k * 768;
        if (u < HD) {
          float di = __ldcg(&d1[u])        + __ldcg(&g_b1[u]);
          float df = __ldcg(&d1[u + 2048]) + __ldcg(&g_b1[u + 2048]);
          float dg = __ldcg(&d1[u + 4096]) + __ldcg(&g_b1[u + 4096]);
          float dz = __ldcg(&d1[u + 6144]) + __ldcg(&g_b1[u + 6144]);
          if (P) {
            di += __ldcg(&P[u]);        df += __ldcg(&P[u + 2048]);
            dg += __ldcg(&P[u + 4096]); dz += __ldcg(&P[u + 6144]);
          }
          float c = sigm(df) * c1r[k] + sigm(di) * tanhf(dg);
          c1r[k] = c;
          sAh[u] = __float2half_rn(sigm(dz) * tanhf(c));
        }
      }
    }
    __syncthreads();   // sAh (h1 new) ready for S3

    // ======== phase 1b: [S3 = Wih2 . h1new] || [zero d1 parity t+1] ========
    if (strm) {
      CONSUME_SEG(sAh, d3);
    } else {
      for (int z = b * 768 + a; z < H4; z += nblk * 768)
        __stcg(&g_d1[pn * H4 + z], 0.f);
    }
    grid_sync();   // gsyncA: d2,d3 complete; d1' zeroed everywhere

    // ======== phase 2: [S1 = Whh1 . h1new -> d1'] || [act2+logits+sample] ===
    if (strm) {
      CONSUME_SEG(sAh, d1n);
    } else {
#pragma unroll
      for (int k = 0; k < 3; k++) {
        const int u = a + k * 768;
        if (u < HD) {
          float di = __ldcg(&d2[u])        + __ldcg(&d3[u])        + __ldcg(&g_b2[u]);
          float df = __ldcg(&d2[u + 2048]) + __ldcg(&d3[u + 2048]) + __ldcg(&g_b2[u + 2048]);
          float dg = __ldcg(&d2[u + 4096]) + __ldcg(&d3[u + 4096]) + __ldcg(&g_b2[u + 4096]);
          float dz = __ldcg(&d2[u + 6144]) + __ldcg(&d3[u + 6144]) + __ldcg(&g_b2[u + 6144]);
          float c = sigm(df) * c2r[k] + sigm(di) * tanhf(dg);
          c2r[k] = c;
          sBh[u] = __float2half_rn(sigm(dz) * tanhf(c));
        }
      }
      asm volatile("bar.sync 1, 768;" ::: "memory");   // sBh ready (crew only)
      if (w < 16) {
        const int j = w - 8;
        const float4* wr = (const float4*)(Wout + ((size_t)t * MAXS + j) * HD);
        const __half2* h2p = (const __half2*)sBh;
        float p = 0.f;
#pragma unroll 4
        for (int i = lane; i < HD / 4; i += 32) {
          float4 aa = __ldg(&wr[i]);
          float2 xf = __half22float2(h2p[2 * i]);
          float2 yf = __half22float2(h2p[2 * i + 1]);
          p += aa.x * xf.x + aa.y * xf.y + aa.z * yf.x + aa.w * yf.y;
        }
#pragma unroll
        for (int off = 16; off; off >>= 1) p += __shfl_xor_sync(0xffffffffu, p, off);
        if (lane == 0) sLG[j] = p + bout[t * MAXS + j];
      } else {
        // warps 16..31: zero d2,d3 parity t+1
        for (int z = b * 512 + (a - 256); z < 2 * H4; z += nblk * 512) {
          if (z < H4) __stcg(&g_d2[pn * H4 + z], 0.f);
          else        __stcg(&g_d3[pn * H4 + (z - H4)], 0.f);
        }
      }
      asm volatile("bar.sync 1, 768;" ::: "memory");   // logits ready
      if (a == 0) {
        const int tp = t & 3;
        const int sz = sizes[tp];
        float l[8];
#pragma unroll
        for (int j = 0; j < 8; j++) l[j] = (j < sz) ? sLG[j] : -1e9f;

        unsigned k0, k1;
        threefry2x32(0u, 1u, 0u, (unsigned)t, &k0, &k1);
        unsigned bits[8];
#pragma unroll
        for (int i = 0; i < 8; i++) {
          unsigned aa, bb;
          threefry2x32(k0, k1, 0u, (unsigned)i, &aa, &bb);
          bits[i] = aa ^ bb;
        }
        float gmb[8];
#pragma unroll
        for (int j = 0; j < 8; j++) {
          unsigned fb = (bits[j] >> 9) | 0x3f800000u;
          float uu = __uint_as_float(fb) - 1.0f;
          uu = fmaxf(TINYF, uu + TINYF);
          gmb[j] = -logf(-logf(uu));
        }
        int best = 0;
        float bv = l[0] + gmb[0];
#pragma unroll
        for (int j = 1; j < 8; j++) {
          float v = l[j] + gmb[j];
          if (v > bv) { bv = v; best = j; }
        }
        float m = l[0];
#pragma unroll
        for (int j = 1; j < 8; j++) m = fmaxf(m, l[j]);
        float s = 0.f;
#pragma unroll
        for (int j = 0; j < 8; j++) s += expf(l[j] - m);
        float prob = expf(l[best] - m) / s;

        *sAR = offs[tp] + best;
        if (b == 0) {
          out[t]      = (float)best;
          out[TT + t] = prob;
        }
      }
    }
    grid_sync();   // gsyncB: d1' complete; sAR published in-block
  }
}

// ------------------------- launch -------------------------------------------
extern "C" void kernel_launch(void* const* d_in, const int* in_sizes, int n_in,
                              void* d_out, int out_size) {
  const float* emb  = (const float*)d_in[0];
  const float* Wih1 = (const float*)d_in[1];
  const float* Whh1 = (const float*)d_in[2];
  const float* bih1 = (const float*)d_in[3];
  const float* bhh1 = (const float*)d_in[4];
  const float* Wih2 = (const float*)d_in[5];
  const float* Whh2 = (const float*)d_in[6];
  const float* bih2 = (const float*)d_in[7];
  const float* bhh2 = (const float*)d_in[8];
  const float* Wout = (const float*)d_in[9];
  const float* bout = (const float*)d_in[10];
  (void)in_sizes; (void)n_in; (void)out_size;

  static int configured = 0;
  if (!configured) {
    cudaFuncSetAttribute(nas_lstm_kernel,
                         cudaFuncAttributeMaxDynamicSharedMemorySize, SMEM_TOTAL);
    configured = 1;
  }

  int dev = 0;
  cudaGetDevice(&dev);
  int sms = 0;
  cudaDeviceGetAttribute(&sms, cudaDevAttrMultiProcessorCount, dev);
  int occ = 0;
  cudaOccupancyMaxActiveBlocksPerMultiprocessor(&occ, nas_lstm_kernel, NTH,
                                                SMEM_TOTAL);
  if (occ < 1) occ = 1;
  int nblk = sms * occ;
  if (nblk > 128) nblk = 128;
  if (nblk < 2) nblk = 2;

  nas_lstm_kernel<<<nblk, NTH, SMEM_TOTAL>>>(emb, Wih1, Whh1, bih1, bhh1,
                                             Wih2, Whh2, bih2, bhh2,
                                             Wout, bout, (float*)d_out);
}

// round 17
// speedup vs baseline: 1.0139x; 1.0025x over previous
#include <cuda_runtime.h>
#include <cuda_fp16.h>
#include <math.h>
#include <stdint.h>

// ---------------------------------------------------------------------------
// NAS-controller LSTM, persistent kernel v17 = v16 + evict_last L2 hints on
// weight TMA loads (v6-verified mechanism; dropped during the v13 ring
// rewrite — DRAM% 30 showed 56MB/step of L2 thrash refetch).
//  - role split: warps 0-7 stream+HMMA, warps 8-31 acts/logits/sample/zeroing
//  - schedule: [S2 || act1] sync [S3 || zero-d1'] gsyncA [S1' || act2+sample]
//  - per-warp 3 x 8KB TMA rings; fp16 a-frag weights; dual-chain HMMA
//  - threefry2x32 partitionable path (verified bit-exact)
// ---------------------------------------------------------------------------

#define HD    2048
#define H4    8192
#define ED    512
#define TT    48
#define MAXS  8
#define NEMB  23
#define NTH   1024
#define NWARPS 32
#define TINYF 1.17549435e-38f

#define NSLOT    3
#define SLICE_B  8192
#define NSTW     8                 // streaming warps per block

// smem layout (bytes)
#define OFF_SAH   0                 // h1 fp16 (4096)
#define OFF_SBH   4096              // h2 fp16
#define OFF_LG    8192
#define OFF_AROW  8224
#define OFF_MBAR  8240              // 8*3*8 = 192
#define OFF_RING  9216              // 8*3*8192 = 196608
#define SMEM_TOTAL (OFF_RING + NSTW * NSLOT * SLICE_B)   // 205824

// ------------------------- device scratch ----------------------------------
__device__ __half   g_Ws[3u * 512 * 128 * 256];  // swizzled fp16 (96MB)
__device__ float    g_P1[NEMB * H4];
__device__ float    g_d1[4 * H4];    // Whh1.h1 partials, 4-step parity ring
__device__ float    g_d2[4 * H4];    // Whh2.h2
__device__ float    g_d3[4 * H4];    // Wih2.h1new
__device__ float    g_b1[H4];
__device__ float    g_b2[H4];
__device__ unsigned g_count = 0;
__device__ unsigned g_gen   = 0;

// ------------------------- grid barrier (v8-proven) -------------------------
__device__ __forceinline__ void grid_sync() {
  __threadfence();
  __syncthreads();
  if (threadIdx.x == 0) {
    volatile unsigned* vg = (volatile unsigned*)&g_gen;
    unsigned gen = *vg;
    __threadfence();
    if (atomicAdd(&g_count, 1u) == (unsigned)(gridDim.x - 1)) {
      g_count = 0u;
      __threadfence();
      atomicAdd(&g_gen, 1u);
    } else {
      while (*vg == gen) { }
    }
  }
  __syncthreads();
}

// ------------------------- mbarrier / bulk copy -----------------------------
__device__ __forceinline__ uint32_t smem_u32(const void* p) {
  uint32_t a;
  asm("{ .reg .u64 t; cvta.to.shared.u64 t, %1; cvt.u32.u64 %0, t; }"
      : "=r"(a) : "l"(p));
  return a;
}
__device__ __forceinline__ void mbar_init(uint32_t a, uint32_t cnt) {
  asm volatile("mbarrier.init.shared.b64 [%0], %1;" :: "r"(a), "r"(cnt) : "memory");
}
__device__ __forceinline__ void mbar_expect(uint32_t a, uint32_t tx) {
  asm volatile("mbarrier.arrive.expect_tx.shared.b64 _, [%0], %1;"
               :: "r"(a), "r"(tx) : "memory");
}
__device__ __forceinline__ void mbar_wait(uint32_t a, unsigned ph) {
  asm volatile(
      "{\n\t.reg .pred P;\n"
      "W%=:\n\t"
      "mbarrier.try_wait.parity.shared.b64 P, [%0], %1;\n\t"
      "@P bra D%=;\n\t"
      "bra W%=;\n"
      "D%=:\n\t}"
      :: "r"(a), "r"(ph) : "memory");
}
__device__ __forceinline__ void bulk_g2s_hint(uint32_t dst, const void* src,
                                              uint32_t bytes, uint32_t bar,
                                              uint64_t pol) {
  asm volatile(
      "cp.async.bulk.shared::cluster.global.mbarrier::complete_tx::bytes"
      ".L2::cache_hint [%0], [%1], %2, [%3], %4;"
      :: "r"(dst), "l"(src), "r"(bytes), "r"(bar), "l"(pol) : "memory");
}

// ------------------------- threefry2x32 (verified exact) --------------------
__device__ __forceinline__ unsigned rotl32(unsigned x, int r) {
  return (x << r) | (x >> (32 - r));
}
__device__ __forceinline__ void threefry2x32(unsigned k0, unsigned k1,
                                             unsigned x0, unsigned x1,
                                             unsigned* o0, unsigned* o1) {
  unsigned ks0 = k0, ks1 = k1, ks2 = k0 ^ k1 ^ 0x1BD11BDAu;
  x0 += ks0; x1 += ks1;
  x0 += x1; x1 = rotl32(x1, 13); x1 ^= x0;
  x0 += x1; x1 = rotl32(x1, 15); x1 ^= x0;
  x0 += x1; x1 = rotl32(x1, 26); x1 ^= x0;
  x0 += x1; x1 = rotl32(x1, 6);  x1 ^= x0;
  x0 += ks1; x1 += ks2 + 1u;
  x0 += x1; x1 = rotl32(x1, 17); x1 ^= x0;
  x0 += x1; x1 = rotl32(x1, 29); x1 ^= x0;
  x0 += x1; x1 = rotl32(x1, 16); x1 ^= x0;
  x0 += x1; x1 = rotl32(x1, 24); x1 ^= x0;
  x0 += ks2; x1 += ks0 + 2u;
  x0 += x1; x1 = rotl32(x1, 13); x1 ^= x0;
  x0 += x1; x1 = rotl32(x1, 15); x1 ^= x0;
  x0 += x1; x1 = rotl32(x1, 26); x1 ^= x0;
  x0 += x1; x1 = rotl32(x1, 6);  x1 ^= x0;
  x0 += ks0; x1 += ks1 + 3u;
  x0 += x1; x1 = rotl32(x1, 17); x1 ^= x0;
  x0 += x1; x1 = rotl32(x1, 29); x1 ^= x0;
  x0 += x1; x1 = rotl32(x1, 16); x1 ^= x0;
  x0 += x1; x1 = rotl32(x1, 24); x1 ^= x0;
  x0 += ks1; x1 += ks2 + 4u;
  x0 += x1; x1 = rotl32(x1, 13); x1 ^= x0;
  x0 += x1; x1 = rotl32(x1, 15); x1 ^= x0;
  x0 += x1; x1 = rotl32(x1, 26); x1 ^= x0;
  x0 += x1; x1 = rotl32(x1, 6);  x1 ^= x0;
  x0 += ks2; x1 += ks0 + 5u;
  *o0 = x0; *o1 = x1;
}

__device__ __forceinline__ float sigm(float x) { return 1.0f / (1.0f + expf(-x)); }

// ------------------------- main persistent kernel ---------------------------
__global__ void __launch_bounds__(NTH, 1)
nas_lstm_kernel(const float* __restrict__ emb,
                const float* __restrict__ Wih1, const float* __restrict__ Whh1,
                const float* __restrict__ bih1, const float* __restrict__ bhh1,
                const float* __restrict__ Wih2, const float* __restrict__ Whh2,
                const float* __restrict__ bih2, const float* __restrict__ bhh2,
                const float* __restrict__ Wout, const float* __restrict__ bout,
                float* __restrict__ out) {
  extern __shared__ __align__(16) char sm[];
  const uint32_t smu = smem_u32(sm);

  const int tid  = threadIdx.x;
  const int b    = blockIdx.x;
  const int w    = tid >> 5;
  const int lane = tid & 31;
  const int nblk = gridDim.x;
  const int totw = nblk * NWARPS;
  const int wgl  = w * nblk + b;

  __half* sAh = (__half*)(sm + OFF_SAH);
  __half* sBh = (__half*)(sm + OFF_SBH);
  float*  sLG = (float*)(sm + OFF_LG);
  int*    sAR = (int*)(sm + OFF_AROW);

  const bool strm = (w < NSTW);
  const uint32_t bar  = smu + OFF_MBAR + (uint32_t)w * NSLOT * 8;
  const uint32_t ring = smu + OFF_RING + (uint32_t)w * NSLOT * SLICE_B;
  const int ringoff   = OFF_RING + w * NSLOT * SLICE_B;

  uint64_t polL;
  asm("createpolicy.fractional.L2::evict_last.b64 %0, 1.0;" : "=l"(polL));

  const int nwst = NSTW * nblk;
  const int g    = strm ? (w * nblk + b) : 0;
  const int nU   = strm ? ((g < 1024) ? ((1024 - 1 - g) / nwst + 1) : 0) : 0;
  const int L    = 12 * nU;
  const int TOTAL = TT * L;

  const int a = tid - NSTW * 32;          // crew index 0..767

  // ---------------- init ----------------
  for (int i = tid; i < HD; i += NTH) {
    sAh[i] = __float2half_rn(0.f);
    sBh[i] = __float2half_rn(0.f);
  }
  for (int i = tid; i < NSTW * NSLOT; i += NTH)
    mbar_init(smu + OFF_MBAR + (uint32_t)i * 8, 1u);
  if (tid == 0) *sAR = -1;
  __syncthreads();
  if (tid == 0)
    asm volatile("fence.proxy.async.shared::cta;" ::: "memory");

  for (int i = b * NTH + tid; i < 4 * H4; i += nblk * NTH) {
    g_d1[i] = 0.f; g_d2[i] = 0.f; g_d3[i] = 0.f;
  }
  for (int i = b * NTH + tid; i < H4; i += nblk * NTH) {
    g_b1[i] = bih1[i] + bhh1[i];
    g_b2[i] = bih2[i] + bhh2[i];
  }

  // fp32 -> fp16 a-frag swizzle (verified)
  {
    uint2* dst = (uint2*)g_Ws;
    const long NQ = 3L * 512 * 8 * 512;
    for (long q = (long)b * NTH + tid; q < NQ; q += (long)nblk * NTH) {
      const int cg   = (int)(q & 511);
      const int r    = (int)((q >> 9) & 7);
      const int tile = (int)((q >> 12) & 511);
      const int mat  = (int)(q >> 21);
      const int c    = cg << 2;
      const int j    = cg >> 2;
      const int Lr   = (r << 2) + ((cg & 1) << 1);
      const int o    = (cg & 2) ? 1 : 0;
      const float* src = (mat == 0) ? Whh1 : (mat == 1) ? Whh2 : Wih2;
      const int R1 = (tile << 4) + r;
      float4 v1 = __ldg((const float4*)(src + ((size_t)R1 << 11) + c));
      float4 v2 = __ldg((const float4*)(src + ((size_t)(R1 + 8) << 11) + c));
      __half2 a1 = __floats2half2_rn(v1.x, v1.y);
      __half2 a2 = __floats2half2_rn(v2.x, v2.y);
      __half2 b1h = __floats2half2_rn(v1.z, v1.w);
      __half2 b2h = __floats2half2_rn(v2.z, v2.w);
      const long blk = ((long)(mat << 9 | tile) * 128 + j) * 64;
      uint2 u2a, u2b;
      u2a.x = *(unsigned*)&a1; u2a.y = *(unsigned*)&a2;
      u2b.x = *(unsigned*)&b1h; u2b.y = *(unsigned*)&b2h;
      dst[blk + (Lr << 1) + o]       = u2a;
      dst[blk + ((Lr + 1) << 1) + o] = u2b;
    }
  }

  // P1 = emb @ Wih1^T (warp per row, fp32)
  for (int r = wgl; r < H4; r += totw) {
    float wreg[16];
    const float* wrow = Wih1 + (size_t)r * ED;
#pragma unroll
    for (int i = 0; i < 16; i++) wreg[i] = wrow[lane + i * 32];
    for (int m = 0; m < NEMB; m++) {
      const float* er = emb + m * ED;
      float p = 0.f;
#pragma unroll
      for (int i = 0; i < 16; i++) p += wreg[i] * er[lane + i * 32];
#pragma unroll
      for (int off = 16; off; off >>= 1) p += __shfl_xor_sync(0xffffffffu, p, off);
      if (lane == 0) g_P1[m * H4 + r] = p;
    }
  }
  grid_sync();

  // stream cursors
  int iss = 0, s_seg = 0, s_k = 0, s_q = 0, i_slot = 0, con_slot = 0;
  unsigned ph = 0;
  float c1r[3] = {0.f, 0.f, 0.f};
  float c2r[3] = {0.f, 0.f, 0.f};

#define ISSUE_NEXT()                                                           \
  do {                                                                         \
    if (iss < TOTAL) {                                                         \
      if (lane == 0) {                                                         \
        const int mt_ = (s_seg == 0) ? 1 : ((s_seg == 1) ? 2 : 0);             \
        const int u_ = g + s_k * nwst;                                         \
        const int T_ = u_ >> 1, kh_ = u_ & 1;                                  \
        const char* src_ = (const char*)g_Ws                                   \
            + (((size_t)((mt_ << 9) | T_)) << 16)                              \
            + ((size_t)kh_ << 15) + ((size_t)s_q << 13);                       \
        mbar_expect(bar + i_slot * 8, SLICE_B);                                \
        bulk_g2s_hint(ring + i_slot * SLICE_B, src_, SLICE_B,                  \
                      bar + i_slot * 8, polL);                                 \
      }                                                                        \
      if (++s_q == 4) {                                                        \
        s_q = 0;                                                               \
        if (++s_k == nU) { s_k = 0; if (++s_seg == 3) s_seg = 0; }             \
      }                                                                        \
      i_slot = (i_slot + 1 == NSLOT) ? 0 : i_slot + 1;                         \
      iss++;                                                                   \
    }                                                                          \
  } while (0)

#define CONSUME_SEG(HSM, DPTR)                                                 \
  do {                                                                         \
    for (int k = 0; k < nU; k++) {                                             \
      const int u = g + k * nwst;                                              \
      const int T = u >> 1;                                                    \
      const int kh = u & 1;                                                    \
      const unsigned* hpk = (const unsigned*)(HSM) + (kh << 9) + (lane & 3);   \
      float p0 = 0.f, p1 = 0.f, p2 = 0.f, p3 = 0.f;                            \
      float q0 = 0.f, q1 = 0.f, q2 = 0.f, q3r = 0.f;                           \
      for (int q3 = 0; q3 < 4; q3++) {                                         \
        mbar_wait(bar + con_slot * 8, (ph >> con_slot) & 1u);                  \
        ph ^= (1u << con_slot);                                                \
        const uint4* wp = (const uint4*)(sm + ringoff + con_slot * SLICE_B) + lane; \
        const unsigned* hq = hpk + (q3 << 7);                                  \
        _Pragma("unroll")                                                      \
        for (int j = 0; j < 16; j += 2) {                                      \
          uint4 aa = wp[j * 32];                                               \
          unsigned f0 = hq[j << 3];                                            \
          unsigned f1 = hq[(j << 3) + 4];                                      \
          asm volatile(                                                        \
              "mma.sync.aligned.m16n8k16.row.col.f32.f16.f16.f32 "             \
              "{%0,%1,%2,%3}, {%4,%5,%6,%7}, {%8,%9}, {%0,%1,%2,%3};"          \
              : "+f"(p0), "+f"(p1), "+f"(p2), "+f"(p3)                         \
              : "r"(aa.x), "r"(aa.y), "r"(aa.z), "r"(aa.w), "r"(f0), "r"(f1)); \
          uint4 ab = wp[(j + 1) * 32];                                         \
          unsigned f2 = hq[(j + 1) << 3];                                      \
          unsigned f3 = hq[((j + 1) << 3) + 4];                                \
          asm volatile(                                                        \
              "mma.sync.aligned.m16n8k16.row.col.f32.f16.f16.f32 "             \
              "{%0,%1,%2,%3}, {%4,%5,%6,%7}, {%8,%9}, {%0,%1,%2,%3};"          \
              : "+f"(q0), "+f"(q1), "+f"(q2), "+f"(q3r)                        \
              : "r"(ab.x), "r"(ab.y), "r"(ab.z), "r"(ab.w), "r"(f2), "r"(f3)); \
        }                                                                      \
        con_slot = (con_slot + 1 == NSLOT) ? 0 : con_slot + 1;                 \
        ISSUE_NEXT();                                                          \
      }                                                                        \
      if ((lane & 3) == 0) {                                                   \
        atomicAdd(&(DPTR)[(T << 4) + (lane >> 2)], p0 + q0);                   \
        atomicAdd(&(DPTR)[(T << 4) + 8 + (lane >> 2)], p2 + q2);               \
      }                                                                        \
    }                                                                          \
  } while (0)

  if (strm && L > 0)
    for (int k = 0; k < NSLOT; k++) ISSUE_NEXT();

  const int sizes[4] = {8, 6, 4, 5};
  const int offs[4]  = {0, 8, 14, 18};

  for (int t = 0; t < TT; t++) {
    const int pb = t & 3;
    const int pn = (t + 1) & 3;
    float* d1 = g_d1 + pb * H4;
    float* d1n = g_d1 + pn * H4;
    float* d2 = g_d2 + pb * H4;
    float* d3 = g_d3 + pb * H4;

    // ======== phase 1a: [S2 = Whh2 . h2prev] || [act1] ========
    if (strm) {
      CONSUME_SEG(sBh, d2);
    } else {
      const int arow = *sAR;
      const float* P = (arow >= 0) ? (g_P1 + (size_t)arow * H4) : (const float*)0;
#pragma unroll
      for (int k = 0; k < 3; k++) {
        const int u = a + k * 768;
        if (u < HD) {
          float di = __ldcg(&d1[u])        + __ldcg(&g_b1[u]);
          float df = __ldcg(&d1[u + 2048]) + __ldcg(&g_b1[u + 2048]);
          float dg = __ldcg(&d1[u + 4096]) + __ldcg(&g_b1[u + 4096]);
          float dz = __ldcg(&d1[u + 6144]) + __ldcg(&g_b1[u + 6144]);
          if (P) {
            di += __ldcg(&P[u]);        df += __ldcg(&P[u + 2048]);
            dg += __ldcg(&P[u + 4096]); dz += __ldcg(&P[u + 6144]);
          }
          float c = sigm(df) * c1r[k] + sigm(di) * tanhf(dg);
          c1r[k] = c;
          sAh[u] = __float2half_rn(sigm(dz) * tanhf(c));
        }
      }
    }
    __syncthreads();   // sAh (h1 new) ready for S3

    // ======== phase 1b: [S3 = Wih2 . h1new] || [zero d1 parity t+1] ========
    if (strm) {
      CONSUME_SEG(sAh, d3);
    } else {
      for (int z = b * 768 + a; z < H4; z += nblk * 768)
        __stcg(&g_d1[pn * H4 + z], 0.f);
    }
    grid_sync();   // gsyncA: d2,d3 complete; d1' zeroed everywhere

    // ======== phase 2: [S1 = Whh1 . h1new -> d1'] || [act2+logits+sample] ===
    if (strm) {
      CONSUME_SEG(sAh, d1n);
    } else {
#pragma unroll
      for (int k = 0; k < 3; k++) {
        const int u = a + k * 768;
        if (u < HD) {
          float di = __ldcg(&d2[u])        + __ldcg(&d3[u])        + __ldcg(&g_b2[u]);
          float df = __ldcg(&d2[u + 2048]) + __ldcg(&d3[u + 2048]) + __ldcg(&g_b2[u + 2048]);
          float dg = __ldcg(&d2[u + 4096]) + __ldcg(&d3[u + 4096]) + __ldcg(&g_b2[u + 4096]);
          float dz = __ldcg(&d2[u + 6144]) + __ldcg(&d3[u + 6144]) + __ldcg(&g_b2[u + 6144]);
          float c = sigm(df) * c2r[k] + sigm(di) * tanhf(dg);
          c2r[k] = c;
          sBh[u] = __float2half_rn(sigm(dz) * tanhf(c));
        }
      }
      asm volatile("bar.sync 1, 768;" ::: "memory");   // sBh ready (crew only)
      if (w < 16) {
        const int j = w - 8;
        const float4* wr = (const float4*)(Wout + ((size_t)t * MAXS + j) * HD);
        const __half2* h2p = (const __half2*)sBh;
        float p = 0.f;
#pragma unroll 4
        for (int i = lane; i < HD / 4; i += 32) {
          float4 aa = __ldg(&wr[i]);
          float2 xf = __half22float2(h2p[2 * i]);
          float2 yf = __half22float2(h2p[2 * i + 1]);
          p += aa.x * xf.x + aa.y * xf.y + aa.z * yf.x + aa.w * yf.y;
        }
#pragma unroll
        for (int off = 16; off; off >>= 1) p += __shfl_xor_sync(0xffffffffu, p, off);
        if (lane == 0) sLG[j] = p + bout[t * MAXS + j];
      } else {
        for (int z = b * 512 + (a - 256); z < 2 * H4; z += nblk * 512) {
          if (z < H4) __stcg(&g_d2[pn * H4 + z], 0.f);
          else        __stcg(&g_d3[pn * H4 + (z - H4)], 0.f);
        }
      }
      asm volatile("bar.sync 1, 768;" ::: "memory");   // logits ready
      if (a == 0) {
        const int tp = t & 3;
        const int sz = sizes[tp];
        float l[8];
#pragma unroll
        for (int j = 0; j < 8; j++) l[j] = (j < sz) ? sLG[j] : -1e9f;

        unsigned k0, k1;
        threefry2x32(0u, 1u, 0u, (unsigned)t, &k0, &k1);
        unsigned bits[8];
#pragma unroll
        for (int i = 0; i < 8; i++) {
          unsigned aa, bb;
          threefry2x32(k0, k1, 0u, (unsigned)i, &aa, &bb);
          bits[i] = aa ^ bb;
        }
        float gmb[8];
#pragma unroll
        for (int j = 0; j < 8; j++) {
          unsigned fb = (bits[j] >> 9) | 0x3f800000u;
          float uu = __uint_as_float(fb) - 1.0f;
          uu = fmaxf(TINYF, uu + TINYF);
          gmb[j] = -logf(-logf(uu));
        }
        int best = 0;
        float bv = l[0] + gmb[0];
#pragma unroll
        for (int j = 1; j < 8; j++) {
          float v = l[j] + gmb[j];
          if (v > bv) { bv = v; best = j; }
        }
        float m = l[0];
#pragma unroll
        for (int j = 1; j < 8; j++) m = fmaxf(m, l[j]);
        float s = 0.f;
#pragma unroll
        for (int j = 0; j < 8; j++) s += expf(l[j] - m);
        float prob = expf(l[best] - m) / s;

        *sAR = offs[tp] + best;
        if (b == 0) {
          out[t]      = (float)best;
          out[TT + t] = prob;
        }
      }
    }
    grid_sync();   // gsyncB: d1' complete; sAR published in-block
  }
}

// ------------------------- launch -------------------------------------------
extern "C" void kernel_launch(void* const* d_in, const int* in_sizes, int n_in,
                              void* d_out, int out_size) {
  const float* emb  = (const float*)d_in[0];
  const float* Wih1 = (const float*)d_in[1];
  const float* Whh1 = (const float*)d_in[2];
  const float* bih1 = (const float*)d_in[3];
  const float* bhh1 = (const float*)d_in[4];
  const float* Wih2 = (const float*)d_in[5];
  const float* Whh2 = (const float*)d_in[6];
  const float* bih2 = (const float*)d_in[7];
  const float* bhh2 = (const float*)d_in[8];
  const float* Wout = (const float*)d_in[9];
  const float* bout = (const float*)d_in[10];
  (void)in_sizes; (void)n_in; (void)out_size;

  static int configured = 0;
  if (!configured) {
    cudaFuncSetAttribute(nas_lstm_kernel,
                         cudaFuncAttributeMaxDynamicSharedMemorySize, SMEM_TOTAL);
    configured = 1;
  }

  int dev = 0;
  cudaGetDevice(&dev);
  int sms = 0;
  cudaDeviceGetAttribute(&sms, cudaDevAttrMultiProcessorCount, dev);
  int occ = 0;
  cudaOccupancyMaxActiveBlocksPerMultiprocessor(&occ, nas_lstm_kernel, NTH,
                                                SMEM_TOTAL);
  if (occ < 1) occ = 1;
  int nblk = sms * occ;
  if (nblk > 128) nblk = 128;
  if (nblk < 2) nblk = 2;

  nas_lstm_kernel<<<nblk, NTH, SMEM_TOTAL>>>(emb, Wih1, Whh1, bih1, bhh1,
                                             Wih2, Whh2, bih2, bhh2,
                                             Wout, bout, (float*)d_out);
}